// round 15
// baseline (speedup 1.0000x reference)
#include <cuda_runtime.h>

// WENO-Z 1-D periodic, B=16 x N=2^20 fp32.
// Persistent single-wave kernel: 1480 CTAs (148 SM x 10 resident), each
// grid-striding over tiles -> zero wave transitions (was 11 waves).
// Loop body = proven R12 math: stride-4 lane packing, aligned LDG.128,
// f2fma diffs, x10-scaled weights, shuffle tail.

#define N_ELEMS   1048576
#define N_MASK    (N_ELEMS - 1)
#define TPB       128
#define VEC       8
#define TILE      (TPB * VEC)                 // 1024
#define NTILES    ((16 * N_ELEMS) / TILE)     // 16384
#define NBLOCKS   (148 * 10)                  // exactly one resident wave

#define EPS 1e-13f

typedef unsigned long long u64;

__device__ __forceinline__ u64 pk(float lo, float hi) {
    u64 r; asm("mov.b64 %0, {%1, %2};" : "=l"(r) : "f"(lo), "f"(hi)); return r;
}
__device__ __forceinline__ void upk(float& lo, float& hi, u64 v) {
    asm("mov.b64 {%0, %1}, %2;" : "=f"(lo), "=f"(hi) : "l"(v));
}
__device__ __forceinline__ u64 f2mul(u64 a, u64 b) {
    u64 d; asm("mul.rn.f32x2 %0, %1, %2;" : "=l"(d) : "l"(a), "l"(b)); return d;
}
__device__ __forceinline__ u64 f2add(u64 a, u64 b) {
    u64 d; asm("add.rn.f32x2 %0, %1, %2;" : "=l"(d) : "l"(a), "l"(b)); return d;
}
__device__ __forceinline__ u64 f2fma(u64 a, u64 b, u64 c) {
    u64 d; asm("fma.rn.f32x2 %0, %1, %2, %3;" : "=l"(d) : "l"(a), "l"(b), "l"(c)); return d;
}
__device__ __forceinline__ u64 f2abs(u64 a) { return a & 0x7FFFFFFF7FFFFFFFULL; }

__global__ void __launch_bounds__(TPB, 10) weno_z_kernel(
    const float* __restrict__ x, float* __restrict__ out)
{
    const int t    = threadIdx.x;
    const int lane = t & 31;

    const u64 Cm1  = pk(-1.0f, -1.0f);
    const u64 C2   = pk(2.0f, 2.0f);
    const u64 C3   = pk(3.0f, 3.0f);
    const u64 C6   = pk(6.0f, 6.0f);
    const u64 C43  = pk(4.0f/3.0f, 4.0f/3.0f);
    const u64 C05  = pk(0.5f, 0.5f);
    const u64 Cm05 = pk(-0.5f, -0.5f);
    const u64 C13  = pk(1.0f/3.0f, 1.0f/3.0f);
    const u64 Cm16 = pk(-1.0f/6.0f, -1.0f/6.0f);
    const u64 Ceps = pk(EPS, EPS);

    for (int tile = blockIdx.x; tile < NTILES; tile += NBLOCKS) {
        const int b     = tile >> 10;            // tile / (N_ELEMS/TILE)
        const int start = (tile & 1023) * TILE;
        const float* xb = x + ((size_t)b << 20);

        const int n0   = start + t * VEC;        // first output index
        const int base = n0 - 4;                 // multiple of 4 -> aligned
        float4 f0  = *reinterpret_cast<const float4*>(xb + ((base)      & N_MASK));
        float4 f1  = *reinterpret_cast<const float4*>(xb + ((base + 4)  & N_MASK));
        float4 f2v = *reinterpret_cast<const float4*>(xb + ((base + 8)  & N_MASK));

        // p12 = x[n0+8] = next lane's f1.x ; lane 31 loads it directly.
        float p12 = __shfl_down_sync(0xFFFFFFFFu, f1.x, 1);
        if (lane == 31) p12 = xb[(base + 12) & N_MASK];

        float p[13];
        p[0]=f0.x;  p[1]=f0.y;  p[2]=f0.z;  p[3]=f0.w;
        p[4]=f1.x;  p[5]=f1.y;  p[6]=f1.z;  p[7]=f1.w;
        p[8]=f2v.x; p[9]=f2v.y; p[10]=f2v.z; p[11]=f2v.w;
        p[12]=p12;

        // PK[i]  = (p[i],  p[i+4]),  i = 1..8
        // PD1[i] = (d1[i], d1[i+4]), i = 2..8   d1[k] = p[k]-p[k-1]
        // PD2[i] = (d2[i], d2[i+4]), i = 2..7   d2[k] = d1[k+1]-d1[k]
        // R = d1^2 + 4/3 d2^2 + eps ; c = d1*d2 ; S = R + 2 d2^2 (i=2..5)
        u64 PK[9], PD1[9], PD2[8], R[8], c[8], S[6];

        #pragma unroll
        for (int i = 1; i <= 8; i++) PK[i] = pk(p[i], p[i + 4]);

        #pragma unroll
        for (int i = 2; i <= 8; i++) PD1[i] = f2fma(PK[i - 1], Cm1, PK[i]);

        #pragma unroll
        for (int i = 2; i <= 7; i++) {
            PD2[i] = f2fma(PD1[i], Cm1, PD1[i + 1]);
            u64 sq = f2mul(PD2[i], PD2[i]);
            R[i] = f2fma(PD1[i], PD1[i], f2fma(sq, C43, Ceps));
            c[i] = f2mul(PD1[i], PD2[i]);
            if (i <= 5) S[i] = f2fma(sq, C2, R[i]);
        }

        float o[VEC];

        #pragma unroll
        for (int q = 0; q < 4; q++) {
            const int k0 = q + 2, k1 = q + 3, k2 = q + 4;
            // lanes: output m = 4+q (lane0), m+4 = 8+q (lane1)

            const u64 IS0 = f2fma(c[k0], C3, S[k0]);
            const u64 IS1 = f2add(R[k1], c[k1]);
            const u64 IS2 = f2fma(c[k2], Cm1, R[k2]);

            const u64 T5 = f2abs(f2fma(IS0, Cm1, IS2));

            // weights scaled x10: d = (1, 6, 3)
            const u64 T6  = f2mul(T5, C6);
            const u64 T3  = f2mul(T5, C3);
            const u64 u0  = f2add(IS0, T5);
            const u64 su1 = f2fma(IS1, C6, T6);
            const u64 su2 = f2fma(IS2, C3, T3);

            const u64 e01 = f2mul(IS0, IS1);
            const u64 e02 = f2mul(IS0, IS2);
            const u64 e12 = f2mul(IS1, IS2);
            const u64 w0 = f2mul(u0,  e12);
            const u64 w1 = f2mul(su1, e02);
            const u64 w2 = f2mul(su2, e01);

            // G = x2 + d1[m-1]/2 ; P0 = G + d2[m-2]/3 ; P1 = G + d2[m-1]/3
            // P2 = x3 - d1[m]/2 - d2[m]/6
            const u64 G  = f2fma(PD1[k1], C05, PK[k1]);
            const u64 P0 = f2fma(PD2[k0], C13, G);
            const u64 P1 = f2fma(PD2[k1], C13, G);
            const u64 P2 = f2fma(PD2[k2], Cm16, f2fma(PD1[k2], Cm05, PK[k2]));

            const u64 num = f2fma(w2, P2, f2fma(w1, P1, f2mul(w0, P0)));
            const u64 den = f2add(f2add(w0, w1), w2);

            float nlo, nhi, dlo, dhi;
            upk(nlo, nhi, num); upk(dlo, dhi, den);
            o[q]     = __fdividef(nlo, dlo);   // output m   = 4+q
            o[q + 4] = __fdividef(nhi, dhi);   // output m+4 = 8+q
        }

        float* ob = out + ((size_t)b << 20) + n0;
        *reinterpret_cast<float4*>(ob)     = make_float4(o[0], o[1], o[2], o[3]);
        *reinterpret_cast<float4*>(ob + 4) = make_float4(o[4], o[5], o[6], o[7]);
    }
}

extern "C" void kernel_launch(void* const* d_in, const int* in_sizes, int n_in,
                              void* d_out, int out_size)
{
    const float* x = (const float*)d_in[0];
    float* out = (float*)d_out;
    weno_z_kernel<<<NBLOCKS, TPB>>>(x, out);
}

// round 16
// speedup vs baseline: 1.0382x; 1.0382x over previous
#include <cuda_runtime.h>

// WENO-Z 1-D periodic, B=16 x N=2^20 fp32.
// R8 structure (stride-4 lane packing, aligned LDG.128, f2fma diffs, VEC=8,
// TPB=128) with the weight block moved to the idle MUFU pipe:
//   a_i = 1 + T5 * rcp(IS_i)   (rcp.approx.f32, 6 MUFU per q)
// replacing the division-free cross-product form (-6 packed fma ops per q).

#define N_ELEMS   1048576
#define N_MASK    (N_ELEMS - 1)
#define TPB       128
#define VEC       8
#define TILE      (TPB * VEC)    // 1024

#define EPS 1e-13f

typedef unsigned long long u64;

__device__ __forceinline__ u64 pk(float lo, float hi) {
    u64 r; asm("mov.b64 %0, {%1, %2};" : "=l"(r) : "f"(lo), "f"(hi)); return r;
}
__device__ __forceinline__ void upk(float& lo, float& hi, u64 v) {
    asm("mov.b64 {%0, %1}, %2;" : "=f"(lo), "=f"(hi) : "l"(v));
}
__device__ __forceinline__ u64 f2mul(u64 a, u64 b) {
    u64 d; asm("mul.rn.f32x2 %0, %1, %2;" : "=l"(d) : "l"(a), "l"(b)); return d;
}
__device__ __forceinline__ u64 f2add(u64 a, u64 b) {
    u64 d; asm("add.rn.f32x2 %0, %1, %2;" : "=l"(d) : "l"(a), "l"(b)); return d;
}
__device__ __forceinline__ u64 f2fma(u64 a, u64 b, u64 c) {
    u64 d; asm("fma.rn.f32x2 %0, %1, %2, %3;" : "=l"(d) : "l"(a), "l"(b), "l"(c)); return d;
}
__device__ __forceinline__ u64 f2abs(u64 a) { return a & 0x7FFFFFFF7FFFFFFFULL; }

__device__ __forceinline__ float frcp(float a) {
    float r; asm("rcp.approx.f32 %0, %1;" : "=f"(r) : "f"(a)); return r;
}
// packed reciprocal via 2 MUFU.RCP (u64 <-> reg-pair aliasing, no real movs)
__device__ __forceinline__ u64 f2rcp(u64 a) {
    float lo, hi; upk(lo, hi, a);
    return pk(frcp(lo), frcp(hi));
}

__global__ void __launch_bounds__(TPB) weno_z_kernel(
    const float* __restrict__ x, float* __restrict__ out)
{
    const int b     = blockIdx.y;
    const int start = blockIdx.x * TILE;
    const float* xb = x + (size_t)b * N_ELEMS;
    const int t     = threadIdx.x;
    const int lane  = t & 31;

    const int n0 = start + t * VEC;      // first output index for this thread
    // p[k] = x[(n0 - 4 + k) & MASK], k = 0..12 ; outputs at p-index m = 4..11
    const int base = n0 - 4;             // multiple of 4 -> 16B-aligned bases
    float4 f0  = *reinterpret_cast<const float4*>(xb + ((base)      & N_MASK));
    float4 f1  = *reinterpret_cast<const float4*>(xb + ((base + 4)  & N_MASK));
    float4 f2v = *reinterpret_cast<const float4*>(xb + ((base + 8)  & N_MASK));

    // p12 = x[n0+8] = next lane's f1.x ; lane 31 loads it directly.
    float p12 = __shfl_down_sync(0xFFFFFFFFu, f1.x, 1);
    if (lane == 31) p12 = xb[(base + 12) & N_MASK];

    float p[13];
    p[0]=f0.x;  p[1]=f0.y;  p[2]=f0.z;  p[3]=f0.w;
    p[4]=f1.x;  p[5]=f1.y;  p[6]=f1.z;  p[7]=f1.w;
    p[8]=f2v.x; p[9]=f2v.y; p[10]=f2v.z; p[11]=f2v.w;
    p[12]=p12;

    const u64 Cm1  = pk(-1.0f, -1.0f);
    const u64 C1   = pk(1.0f, 1.0f);
    const u64 C2   = pk(2.0f, 2.0f);
    const u64 C3   = pk(3.0f, 3.0f);
    const u64 C6   = pk(6.0f, 6.0f);
    const u64 C43  = pk(4.0f/3.0f, 4.0f/3.0f);
    const u64 C05  = pk(0.5f, 0.5f);
    const u64 Cm05 = pk(-0.5f, -0.5f);
    const u64 C13  = pk(1.0f/3.0f, 1.0f/3.0f);
    const u64 Cm16 = pk(-1.0f/6.0f, -1.0f/6.0f);
    const u64 Ceps = pk(EPS, EPS);

    // PK[i]  = (p[i],  p[i+4]),  i = 1..8
    // PD1[i] = (d1[i], d1[i+4]), i = 2..8   d1[k] = p[k]-p[k-1]
    // PD2[i] = (d2[i], d2[i+4]), i = 2..7   d2[k] = d1[k+1]-d1[k]
    // R[i]   = d1^2 + 4/3 d2^2 + eps ; c[i] = d1*d2 ; S[i] = R + 2 d2^2 (i=2..5)
    u64 PK[9], PD1[9], PD2[8], R[8], c[8], S[6];

    #pragma unroll
    for (int i = 1; i <= 8; i++) PK[i] = pk(p[i], p[i + 4]);

    #pragma unroll
    for (int i = 2; i <= 8; i++) PD1[i] = f2fma(PK[i - 1], Cm1, PK[i]);

    #pragma unroll
    for (int i = 2; i <= 7; i++) {
        PD2[i] = f2fma(PD1[i], Cm1, PD1[i + 1]);
        u64 sq = f2mul(PD2[i], PD2[i]);
        R[i] = f2fma(PD1[i], PD1[i], f2fma(sq, C43, Ceps));
        c[i] = f2mul(PD1[i], PD2[i]);
        if (i <= 5) S[i] = f2fma(sq, C2, R[i]);
    }

    float o[VEC];

    #pragma unroll
    for (int q = 0; q < 4; q++) {
        const int k0 = q + 2, k1 = q + 3, k2 = q + 4;
        // lanes: output m = 4+q (lane0), m+4 = 8+q (lane1) — all operands aligned

        const u64 IS0 = f2fma(c[k0], C3, S[k0]);
        const u64 IS1 = f2add(R[k1], c[k1]);
        const u64 IS2 = f2fma(c[k2], Cm1, R[k2]);

        const u64 T5 = f2abs(f2fma(IS0, Cm1, IS2));

        // relative weights a_i = 1 + T5/IS_i via MUFU rcp (idle pipe);
        // d = (1, 6, 3) folded into den/num combiners.
        const u64 a0 = f2fma(T5, f2rcp(IS0), C1);
        const u64 a1 = f2fma(T5, f2rcp(IS1), C1);
        const u64 a2 = f2fma(T5, f2rcp(IS2), C1);

        u64 den = f2fma(a1, C6, a0);
        den     = f2fma(a2, C3, den);

        // G = x2 + d1[m-1]/2 ; P0 = G + d2[m-2]/3 ; P1 = G + d2[m-1]/3
        // P2 = x3 - d1[m]/2 - d2[m]/6
        const u64 G  = f2fma(PD1[k1], C05, PK[k1]);
        const u64 P0 = f2fma(PD2[k0], C13, G);
        const u64 P1 = f2fma(PD2[k1], C13, G);
        const u64 P2 = f2fma(PD2[k2], Cm16, f2fma(PD1[k2], Cm05, PK[k2]));

        const u64 s1 = f2mul(a1, P1);
        const u64 s2 = f2mul(a2, P2);
        u64 num = f2mul(a0, P0);
        num     = f2fma(s1, C6, num);
        num     = f2fma(s2, C3, num);

        float nlo, nhi, dlo, dhi;
        upk(nlo, nhi, num); upk(dlo, dhi, den);
        o[q]     = __fdividef(nlo, dlo);   // output m   = 4+q
        o[q + 4] = __fdividef(nhi, dhi);   // output m+4 = 8+q
    }

    float* ob = out + (size_t)b * N_ELEMS + n0;
    *reinterpret_cast<float4*>(ob)     = make_float4(o[0], o[1], o[2], o[3]);
    *reinterpret_cast<float4*>(ob + 4) = make_float4(o[4], o[5], o[6], o[7]);
}

extern "C" void kernel_launch(void* const* d_in, const int* in_sizes, int n_in,
                              void* d_out, int out_size)
{
    const float* x = (const float*)d_in[0];
    float* out = (float*)d_out;
    const int total = in_sizes[0];
    const int batches = total / N_ELEMS;

    dim3 grid(N_ELEMS / TILE, batches);
    weno_z_kernel<<<grid, TPB>>>(x, out);
}

// round 17
// speedup vs baseline: 1.2094x; 1.1648x over previous
#include <cuda_runtime.h>

// WENO-Z 1-D periodic, B=16 x N=2^20 fp32.  FINAL (R8 lock-in).
// Stride-4 lane packing: pack outputs (m, m+4) so every packed operand is
// consumed at identical lane alignment -> zero realignment movs.
// Direct aligned LDG.128 (L1/L2 dedup the stencil overlaps), packed f32x2
// difference-form math, division-free WENO weights, fast final divide.

#define N_ELEMS   1048576
#define N_MASK    (N_ELEMS - 1)
#define TPB       128
#define VEC       8
#define TILE      (TPB * VEC)    // 1024

#define EPS 1e-13f

typedef unsigned long long u64;

__device__ __forceinline__ u64 pk(float lo, float hi) {
    u64 r; asm("mov.b64 %0, {%1, %2};" : "=l"(r) : "f"(lo), "f"(hi)); return r;
}
__device__ __forceinline__ void upk(float& lo, float& hi, u64 v) {
    asm("mov.b64 {%0, %1}, %2;" : "=f"(lo), "=f"(hi) : "l"(v));
}
__device__ __forceinline__ u64 f2mul(u64 a, u64 b) {
    u64 d; asm("mul.rn.f32x2 %0, %1, %2;" : "=l"(d) : "l"(a), "l"(b)); return d;
}
__device__ __forceinline__ u64 f2add(u64 a, u64 b) {
    u64 d; asm("add.rn.f32x2 %0, %1, %2;" : "=l"(d) : "l"(a), "l"(b)); return d;
}
__device__ __forceinline__ u64 f2fma(u64 a, u64 b, u64 c) {
    u64 d; asm("fma.rn.f32x2 %0, %1, %2, %3;" : "=l"(d) : "l"(a), "l"(b), "l"(c)); return d;
}
__device__ __forceinline__ u64 f2abs(u64 a) { return a & 0x7FFFFFFF7FFFFFFFULL; }

__global__ void __launch_bounds__(TPB) weno_z_kernel(
    const float* __restrict__ x, float* __restrict__ out)
{
    const int b     = blockIdx.y;
    const int start = blockIdx.x * TILE;
    const float* xb = x + (size_t)b * N_ELEMS;
    const int t     = threadIdx.x;

    const int n0 = start + t * VEC;      // first output index for this thread
    // p[k] = x[(n0 - 4 + k) & MASK], k = 0..12 ; outputs at p-index m = 4..11
    const int base = n0 - 4;             // multiple of 4 -> 16B-aligned bases
    float4 f0  = *reinterpret_cast<const float4*>(xb + ((base)      & N_MASK));
    float4 f1  = *reinterpret_cast<const float4*>(xb + ((base + 4)  & N_MASK));
    float4 f2v = *reinterpret_cast<const float4*>(xb + ((base + 8)  & N_MASK));
    float p12  = xb[(base + 12) & N_MASK];

    float p[13];
    p[0]=f0.x;  p[1]=f0.y;  p[2]=f0.z;  p[3]=f0.w;
    p[4]=f1.x;  p[5]=f1.y;  p[6]=f1.z;  p[7]=f1.w;
    p[8]=f2v.x; p[9]=f2v.y; p[10]=f2v.z; p[11]=f2v.w;
    p[12]=p12;

    const u64 Cm1  = pk(-1.0f, -1.0f);
    const u64 C2   = pk(2.0f, 2.0f);
    const u64 C3   = pk(3.0f, 3.0f);
    const u64 C43  = pk(4.0f/3.0f, 4.0f/3.0f);
    const u64 C05  = pk(0.5f, 0.5f);
    const u64 Cm05 = pk(-0.5f, -0.5f);
    const u64 C13  = pk(1.0f/3.0f, 1.0f/3.0f);
    const u64 Cm16 = pk(-1.0f/6.0f, -1.0f/6.0f);
    const u64 Ceps = pk(EPS, EPS);
    const u64 Cd0  = pk(0.1f, 0.1f);
    const u64 Cd1  = pk(0.6f, 0.6f);
    const u64 Cd2  = pk(0.3f, 0.3f);

    // PK[i]  = (p[i],  p[i+4]),  i = 1..8
    // PD1[i] = (d1[i], d1[i+4]), i = 2..8   d1[k] = p[k]-p[k-1]
    // PD2[i] = (d2[i], d2[i+4]), i = 2..7   d2[k] = d1[k+1]-d1[k]
    // R[i]   = d1^2 + 4/3 d2^2 + eps ; c[i] = d1*d2 ; S[i] = R + 2 d2^2 (i=2..5)
    u64 PK[9], PD1[9], PD2[8], R[8], c[8], S[6];

    #pragma unroll
    for (int i = 1; i <= 8; i++) PK[i] = pk(p[i], p[i + 4]);

    #pragma unroll
    for (int i = 2; i <= 8; i++) PD1[i] = f2fma(PK[i - 1], Cm1, PK[i]);

    #pragma unroll
    for (int i = 2; i <= 7; i++) {
        PD2[i] = f2fma(PD1[i], Cm1, PD1[i + 1]);
        u64 sq = f2mul(PD2[i], PD2[i]);
        R[i] = f2fma(PD1[i], PD1[i], f2fma(sq, C43, Ceps));
        c[i] = f2mul(PD1[i], PD2[i]);
        if (i <= 5) S[i] = f2fma(sq, C2, R[i]);
    }

    float o[VEC];

    #pragma unroll
    for (int q = 0; q < 4; q++) {
        const int k0 = q + 2, k1 = q + 3, k2 = q + 4;
        // lanes: output m = 4+q (lane0), m+4 = 8+q (lane1) — all operands aligned

        const u64 IS0 = f2fma(c[k0], C3, S[k0]);
        const u64 IS1 = f2add(R[k1], c[k1]);
        const u64 IS2 = f2fma(c[k2], Cm1, R[k2]);

        const u64 T5 = f2abs(f2fma(IS0, Cm1, IS2));

        const u64 t0 = f2add(IS0, T5);
        const u64 t1 = f2add(IS1, T5);
        const u64 t2 = f2add(IS2, T5);
        const u64 g0 = f2mul(Cd0, t0);
        const u64 g1 = f2mul(Cd1, t1);
        const u64 g2 = f2mul(Cd2, t2);
        const u64 e01 = f2mul(IS0, IS1);
        const u64 e02 = f2mul(IS0, IS2);
        const u64 e12 = f2mul(IS1, IS2);
        const u64 w0 = f2mul(g0, e12);
        const u64 w1 = f2mul(g1, e02);
        const u64 w2 = f2mul(g2, e01);

        // G = x2 + d1[m-1]/2 ; P0 = G + d2[m-2]/3 ; P1 = G + d2[m-1]/3
        // P2 = x3 - d1[m]/2 - d2[m]/6
        const u64 G  = f2fma(PD1[k1], C05, PK[k1]);
        const u64 P0 = f2fma(PD2[k0], C13, G);
        const u64 P1 = f2fma(PD2[k1], C13, G);
        const u64 P2 = f2fma(PD2[k2], Cm16, f2fma(PD1[k2], Cm05, PK[k2]));

        const u64 num = f2fma(w2, P2, f2fma(w1, P1, f2mul(w0, P0)));
        const u64 den = f2add(f2add(w0, w1), w2);

        float nlo, nhi, dlo, dhi;
        upk(nlo, nhi, num); upk(dlo, dhi, den);
        o[q]     = __fdividef(nlo, dlo);   // output m   = 4+q
        o[q + 4] = __fdividef(nhi, dhi);   // output m+4 = 8+q
    }

    float* ob = out + (size_t)b * N_ELEMS + n0;
    *reinterpret_cast<float4*>(ob)     = make_float4(o[0], o[1], o[2], o[3]);
    *reinterpret_cast<float4*>(ob + 4) = make_float4(o[4], o[5], o[6], o[7]);
}

extern "C" void kernel_launch(void* const* d_in, const int* in_sizes, int n_in,
                              void* d_out, int out_size)
{
    const float* x = (const float*)d_in[0];
    float* out = (float*)d_out;
    const int total = in_sizes[0];
    const int batches = total / N_ELEMS;

    dim3 grid(N_ELEMS / TILE, batches);
    weno_z_kernel<<<grid, TPB>>>(x, out);
}